// round 2
// baseline (speedup 1.0000x reference)
#include <cuda_runtime.h>
#include <math.h>

#define BATCH 16
#define NC    2048
#define NT    2048
#define TG    2048
#define NBINS 128
#define RFAC  7.5f     // cutoff radius = RFAC * ls ; exp(-0.5*RFAC^2) < 1e-11
#define EPS   1e-8f

// ---------------- scratch (no allocs allowed) ----------------
__device__ float g_minmax[2];                 // [lower, upper]
__device__ int   g_counts[BATCH * NBINS];
__device__ int   g_starts[BATCH * (NBINS + 1)];
__device__ int   g_cursor[BATCH * NBINS];
__device__ float g_sx[BATCH * NC];            // xc sorted by bin
__device__ float g_sy[BATCH * NC];            // yc permuted alongside
__device__ float g_h0[BATCH * TG];
__device__ float g_h1[BATCH * TG];
__device__ float g_fmu[BATCH * TG];
__device__ float g_fsp[BATCH * TG];           // softplus(f_sigma)

// ---------------- float atomics ----------------
__device__ __forceinline__ void atomicMaxF(float* a, float v) {
    if (v >= 0.f) atomicMax((int*)a, __float_as_int(v));
    else          atomicMin((unsigned int*)a, __float_as_uint(v));
}
__device__ __forceinline__ void atomicMinF(float* a, float v) {
    if (v >= 0.f) atomicMin((int*)a, __float_as_int(v));
    else          atomicMax((unsigned int*)a, __float_as_uint(v));
}

// ---------------- K0: reset scratch ----------------
__global__ void init_kernel() {
    int i = blockIdx.x * blockDim.x + threadIdx.x;
    if (i == 0) g_minmax[0] = INFINITY;
    if (i == 1) g_minmax[1] = -INFINITY;
    if (i < BATCH * NBINS) g_counts[i] = 0;
}

// ---------------- K1: global min/max over xc and xt ----------------
__global__ void minmax_kernel(const float* __restrict__ xc,
                              const float* __restrict__ xt) {
    const int n = BATCH * NC, m = BATCH * NT;
    float lo = INFINITY, hi = -INFINITY;
    for (int i = blockIdx.x * blockDim.x + threadIdx.x; i < n + m;
         i += gridDim.x * blockDim.x) {
        float v = (i < n) ? __ldg(&xc[i]) : __ldg(&xt[i - n]);
        lo = fminf(lo, v);
        hi = fmaxf(hi, v);
    }
    #pragma unroll
    for (int off = 16; off; off >>= 1) {
        lo = fminf(lo, __shfl_xor_sync(0xffffffffu, lo, off));
        hi = fmaxf(hi, __shfl_xor_sync(0xffffffffu, hi, off));
    }
    __shared__ float slo[8], shi[8];
    int w = threadIdx.x >> 5, lane = threadIdx.x & 31;
    if (lane == 0) { slo[w] = lo; shi[w] = hi; }
    __syncthreads();
    if (threadIdx.x == 0) {
        int nw = blockDim.x >> 5;
        for (int k = 1; k < nw; k++) { lo = fminf(lo, slo[k]); hi = fmaxf(hi, shi[k]); }
        atomicMinF(&g_minmax[0], lo);
        atomicMaxF(&g_minmax[1], hi);
    }
}

__device__ __forceinline__ int bin_of(float x, float lower, float invw) {
    int b = (int)((x - lower) * invw);
    return min(NBINS - 1, max(0, b));
}

// ---------------- K2: histogram of xc ----------------
__global__ void hist_kernel(const float* __restrict__ xc) {
    float lower = g_minmax[0];
    float invw = (float)NBINS / (g_minmax[1] - lower);
    for (int i = blockIdx.x * blockDim.x + threadIdx.x; i < BATCH * NC;
         i += gridDim.x * blockDim.x) {
        int b = i >> 11;  // / NC
        atomicAdd(&g_counts[b * NBINS + bin_of(__ldg(&xc[i]), lower, invw)], 1);
    }
}

// ---------------- K3: per-batch exclusive scan (tiny) ----------------
__global__ void prefix_kernel() {
    int b = blockIdx.x;
    if (threadIdx.x == 0) {
        int run = 0;
        for (int i = 0; i < NBINS; i++) {
            g_starts[b * (NBINS + 1) + i] = run;
            g_cursor[b * NBINS + i] = run;
            run += g_counts[b * NBINS + i];
        }
        g_starts[b * (NBINS + 1) + NBINS] = run;
    }
}

// ---------------- K4: scatter (counting sort) ----------------
__global__ void scatter_kernel(const float* __restrict__ xc,
                               const float* __restrict__ yc) {
    float lower = g_minmax[0];
    float invw = (float)NBINS / (g_minmax[1] - lower);
    for (int i = blockIdx.x * blockDim.x + threadIdx.x; i < BATCH * NC;
         i += gridDim.x * blockDim.x) {
        int b = i >> 11;
        float x = __ldg(&xc[i]);
        int pos = atomicAdd(&g_cursor[b * NBINS + bin_of(x, lower, invw)], 1);
        g_sx[b * NC + pos] = x;
        g_sy[b * NC + pos] = __ldg(&yc[i]);
    }
}

// ---------------- K5: psi stage — h0, h1 over truncated window ----------------
__global__ void psi_kernel(const float* __restrict__ pls,
                           const float* __restrict__ pos_) {
    int gw = (blockIdx.x * blockDim.x + threadIdx.x) >> 5;  // one warp per t-point
    int lane = threadIdx.x & 31;
    if (gw >= BATCH * TG) return;
    int b = gw >> 11, i = gw & (TG - 1);

    float lower = g_minmax[0], upper = g_minmax[1];
    float range = upper - lower;
    float dt = range / (float)(TG - 1);
    float t = lower + i * dt;
    float ls = __ldg(pls), osv = __ldg(pos_);
    float inv2 = 0.5f / (ls * ls);
    float R = fabsf(ls) * RFAC;
    float invw = (float)NBINS / range;

    int blo = max(0, (int)floorf((t - R - lower) * invw));
    int bhi = min(NBINS - 1, (int)floorf((t + R - lower) * invw));
    int s = g_starts[b * (NBINS + 1) + blo];
    int e = g_starts[b * (NBINS + 1) + bhi + 1];

    const float* sx = g_sx + b * NC;
    const float* sy = g_sy + b * NC;
    float a0 = 0.f, a1 = 0.f;
    for (int k = s + lane; k < e; k += 32) {
        float xk = __ldg(&sx[k]);
        float yk = __ldg(&sy[k]);
        float d = t - xk;
        float ev = osv * __expf(-d * d * inv2);
        a0 += ev;
        a1 += ev * yk;
    }
    #pragma unroll
    for (int off = 16; off; off >>= 1) {
        a0 += __shfl_xor_sync(0xffffffffu, a0, off);
        a1 += __shfl_xor_sync(0xffffffffu, a1, off);
    }
    if (lane == 0) {
        g_h0[gw] = a0;
        g_h1[gw] = a1 / (a0 + EPS);
    }
}

// ---------------- K6: fused 4-layer conv chain ----------------
#define T_TILE 128
#define HALO   8
#define CW     (T_TILE + 2 * HALO)  // 144

__global__ __launch_bounds__(128) void conv_kernel(
    const float* __restrict__ w1, const float* __restrict__ b1,
    const float* __restrict__ w2, const float* __restrict__ b2,
    const float* __restrict__ w3, const float* __restrict__ b3,
    const float* __restrict__ w4, const float* __restrict__ b4) {
    __shared__ float s0[3][CW];
    __shared__ float s1[16][CW];   // layer1 out, later reused for layer3 out
    __shared__ float s2[32][CW];

    const int tiles = TG / T_TILE;  // 16
    int b = blockIdx.x / tiles;
    int tile = blockIdx.x % tiles;
    int p0 = tile * T_TILE - HALO;  // global pos of local u=0
    int tid = threadIdx.x;
    const int NTH = 128;

    float lower = g_minmax[0];
    float dt = (g_minmax[1] - lower) / (float)(TG - 1);

    // load input channels (t, h0, h1); zero outside [0, TG)
    for (int u = tid; u < CW; u += NTH) {
        int p = p0 + u;
        bool in = (p >= 0 && p < TG);
        s0[0][u] = in ? (lower + p * dt) : 0.f;
        s0[1][u] = in ? g_h0[b * TG + p] : 0.f;
        s0[2][u] = in ? g_h1[b * TG + p] : 0.f;
    }
    __syncthreads();

    // layer 1: 3 -> 16, valid u in [2, CW-2)
    {
        const int nv = CW - 4;
        for (int idx = tid; idx < 16 * nv; idx += NTH) {
            int co = idx / nv, u = 2 + idx % nv;
            float acc = __ldg(&b1[co]);
            #pragma unroll
            for (int ci = 0; ci < 3; ci++)
                #pragma unroll
                for (int k = 0; k < 5; k++)
                    acc += __ldg(&w1[(co * 3 + ci) * 5 + k]) * s0[ci][u - 2 + k];
            int p = p0 + u;
            s1[co][u] = (p >= 0 && p < TG) ? fmaxf(acc, 0.f) : 0.f;
        }
    }
    __syncthreads();

    // layer 2: 16 -> 32, valid u in [4, CW-4)
    {
        const int nv = CW - 8;
        for (int idx = tid; idx < 32 * nv; idx += NTH) {
            int co = idx / nv, u = 4 + idx % nv;
            float acc = __ldg(&b2[co]);
            #pragma unroll
            for (int ci = 0; ci < 16; ci++)
                #pragma unroll
                for (int k = 0; k < 5; k++)
                    acc += __ldg(&w2[(co * 16 + ci) * 5 + k]) * s1[ci][u - 2 + k];
            int p = p0 + u;
            s2[co][u] = (p >= 0 && p < TG) ? fmaxf(acc, 0.f) : 0.f;
        }
    }
    __syncthreads();

    // layer 3: 32 -> 16, valid u in [6, CW-6); writes back into s1
    {
        const int nv = CW - 12;
        for (int idx = tid; idx < 16 * nv; idx += NTH) {
            int co = idx / nv, u = 6 + idx % nv;
            float acc = __ldg(&b3[co]);
            #pragma unroll
            for (int ci = 0; ci < 32; ci++)
                #pragma unroll
                for (int k = 0; k < 5; k++)
                    acc += __ldg(&w3[(co * 32 + ci) * 5 + k]) * s2[ci][u - 2 + k];
            int p = p0 + u;
            s1[co][u] = (p >= 0 && p < TG) ? fmaxf(acc, 0.f) : 0.f;
        }
    }
    __syncthreads();

    // layer 4: 16 -> 2, valid u in [HALO, HALO+T_TILE)
    for (int idx = tid; idx < 2 * T_TILE; idx += NTH) {
        int co = idx / T_TILE, u = HALO + idx % T_TILE;
        float acc = __ldg(&b4[co]);
        #pragma unroll
        for (int ci = 0; ci < 16; ci++)
            #pragma unroll
            for (int k = 0; k < 5; k++)
                acc += __ldg(&w4[(co * 16 + ci) * 5 + k]) * s1[ci][u - 2 + k];
        int p = p0 + u;
        if (co == 0) {
            g_fmu[b * TG + p] = acc;
        } else {
            // softplus(x) = max(x,0) + log1p(exp(-|x|))
            g_fsp[b * TG + p] = fmaxf(acc, 0.f) + log1pf(__expf(-fabsf(acc)));
        }
    }
}

// ---------------- K7: rho stage — mu/sigma over truncated t-window ----------------
__global__ void rho_kernel(const float* __restrict__ xt,
                           const float* __restrict__ pls,
                           const float* __restrict__ pos_,
                           float* __restrict__ out) {
    int gw = (blockIdx.x * blockDim.x + threadIdx.x) >> 5;  // one warp per target
    int lane = threadIdx.x & 31;
    if (gw >= BATCH * NT) return;
    int b = gw >> 11;

    float lower = g_minmax[0];
    float dt = (g_minmax[1] - lower) / (float)(TG - 1);
    float x = __ldg(&xt[gw]);
    float ls = __ldg(pls), osv = __ldg(pos_);
    float inv2 = 0.5f / (ls * ls);
    float R = fabsf(ls) * RFAC;

    int ilo = max(0, (int)ceilf((x - R - lower) / dt));
    int ihi = min(TG - 1, (int)floorf((x + R - lower) / dt));

    const float* fm = g_fmu + b * TG;
    const float* fs = g_fsp + b * TG;
    float mu = 0.f, sg = 0.f;
    for (int i = ilo + lane; i <= ihi; i += 32) {
        float vm = __ldg(&fm[i]);
        float vs = __ldg(&fs[i]);
        float d = x - (lower + i * dt);
        float ev = osv * __expf(-d * d * inv2);
        mu += ev * vm;
        sg += ev * vs;
    }
    #pragma unroll
    for (int off = 16; off; off >>= 1) {
        mu += __shfl_xor_sync(0xffffffffu, mu, off);
        sg += __shfl_xor_sync(0xffffffffu, sg, off);
    }
    if (lane == 0) {
        out[gw * 2 + 0] = mu;
        out[gw * 2 + 1] = sg;
    }
}

// ---------------- launch ----------------
extern "C" void kernel_launch(void* const* d_in, const int* in_sizes, int n_in,
                              void* d_out, int out_size) {
    const float* xc = (const float*)d_in[0];
    const float* yc = (const float*)d_in[1];
    const float* xt = (const float*)d_in[2];
    const float* ls_psi = (const float*)d_in[3];
    const float* os_psi = (const float*)d_in[4];
    const float* ls_rho = (const float*)d_in[5];
    const float* os_rho = (const float*)d_in[6];
    const float* w1 = (const float*)d_in[7];
    const float* b1 = (const float*)d_in[8];
    const float* w2 = (const float*)d_in[9];
    const float* b2 = (const float*)d_in[10];
    const float* w3 = (const float*)d_in[11];
    const float* b3 = (const float*)d_in[12];
    const float* w4 = (const float*)d_in[13];
    const float* b4 = (const float*)d_in[14];
    float* out = (float*)d_out;

    init_kernel<<<8, 256>>>();
    minmax_kernel<<<256, 256>>>(xc, xt);
    hist_kernel<<<128, 256>>>(xc);
    prefix_kernel<<<BATCH, 32>>>();
    scatter_kernel<<<128, 256>>>(xc, yc);
    psi_kernel<<<(BATCH * TG) / 8, 256>>>(ls_psi, os_psi);
    conv_kernel<<<BATCH * (TG / T_TILE), 128>>>(w1, b1, w2, b2, w3, b3, w4, b4);
    rho_kernel<<<(BATCH * NT) / 8, 256>>>(xt, ls_rho, os_rho, out);
}

// round 3
// speedup vs baseline: 1.2056x; 1.2056x over previous
#include <cuda_runtime.h>
#include <math.h>

#define BATCH 16
#define NC    2048
#define NT    2048
#define TG    2048
#define NBINS 128
#define RFAC  7.5f     // cutoff radius = RFAC * ls ; exp(-0.5*RFAC^2) < 1e-11
#define EPS   1e-8f

// Fixed binning: xc, xt are uniform in [0, 128). Bin width = 1.0.
// Clamping makes this correct (if slower) even for out-of-range data:
// out-of-range points land in edge bins and contribute exp(-big) ~ 0.
__device__ __forceinline__ int bin_fix(float x) {
    int b = (int)floorf(x);
    return min(NBINS - 1, max(0, b));
}

// ---------------- scratch (no allocs allowed) ----------------
__device__ float g_minmax[2];                    // [lower, upper] (final)
__device__ float g_plo[BATCH], g_phi[BATCH];     // per-batch partials
__device__ int   g_counts[BATCH * NBINS];
__device__ int   g_starts[BATCH * (NBINS + 1)];
__device__ float g_sx[BATCH * NC];               // xc sorted by bin
__device__ float g_sy[BATCH * NC];               // yc permuted alongside
__device__ float g_h0[BATCH * TG];
__device__ float g_h1[BATCH * TG];
__device__ float g_fmu[BATCH * TG];
__device__ float g_fsp[BATCH * TG];              // softplus(f_sigma)

// ---------------- K1: per-batch histogram + min/max partials ----------------
__global__ __launch_bounds__(256) void hist_minmax_kernel(
    const float* __restrict__ xc, const float* __restrict__ xt) {
    __shared__ int scnt[NBINS];
    __shared__ float slo[8], shi[8];
    int b = blockIdx.x, tid = threadIdx.x;

    for (int i = tid; i < NBINS; i += 256) scnt[i] = 0;
    __syncthreads();

    const float* xcb = xc + b * NC;
    const float* xtb = xt + b * NT;
    float lo = INFINITY, hi = -INFINITY;
    for (int i = tid; i < NC; i += 256) {
        float v = __ldg(&xcb[i]);
        lo = fminf(lo, v); hi = fmaxf(hi, v);
        atomicAdd(&scnt[bin_fix(v)], 1);
    }
    for (int i = tid; i < NT; i += 256) {
        float v = __ldg(&xtb[i]);
        lo = fminf(lo, v); hi = fmaxf(hi, v);
    }
    #pragma unroll
    for (int off = 16; off; off >>= 1) {
        lo = fminf(lo, __shfl_xor_sync(0xffffffffu, lo, off));
        hi = fmaxf(hi, __shfl_xor_sync(0xffffffffu, hi, off));
    }
    int w = tid >> 5, lane = tid & 31;
    if (lane == 0) { slo[w] = lo; shi[w] = hi; }
    __syncthreads();
    if (tid == 0) {
        #pragma unroll
        for (int k = 1; k < 8; k++) { lo = fminf(lo, slo[k]); hi = fmaxf(hi, shi[k]); }
        g_plo[b] = lo; g_phi[b] = hi;
    }
    for (int i = tid; i < NBINS; i += 256) g_counts[b * NBINS + i] = scnt[i];
}

// ---------------- K2: per-batch prefix scan + scatter (counting sort) ----------------
__global__ __launch_bounds__(256) void prefix_scatter_kernel(
    const float* __restrict__ xc, const float* __restrict__ yc) {
    __shared__ int scur[NBINS];
    __shared__ int sstart[NBINS];
    __shared__ int wsum[8];
    int b = blockIdx.x, tid = threadIdx.x;
    int lane = tid & 31, w = tid >> 5;

    // block 0 thread 0 folds the per-batch min/max partials
    if (b == 0 && tid == 0) {
        float lo = INFINITY, hi = -INFINITY;
        #pragma unroll
        for (int k = 0; k < BATCH; k++) {
            lo = fminf(lo, g_plo[k]); hi = fmaxf(hi, g_phi[k]);
        }
        g_minmax[0] = lo; g_minmax[1] = hi;
    }

    // parallel exclusive scan of 128 counts (threads >=128 carry 0)
    int c = (tid < NBINS) ? g_counts[b * NBINS + tid] : 0;
    int v = c;
    #pragma unroll
    for (int off = 1; off < 32; off <<= 1) {
        int n = __shfl_up_sync(0xffffffffu, v, off);
        if (lane >= off) v += n;
    }
    if (lane == 31) wsum[w] = v;
    __syncthreads();
    if (tid == 0) {
        int run = 0;
        #pragma unroll
        for (int k = 0; k < 8; k++) { int t = wsum[k]; wsum[k] = run; run += t; }
    }
    __syncthreads();
    if (tid < NBINS) {
        int excl = v - c + wsum[w];
        sstart[tid] = excl;
        scur[tid] = excl;
        g_starts[b * (NBINS + 1) + tid] = excl;
    }
    if (tid == 0) g_starts[b * (NBINS + 1) + NBINS] = NC;
    __syncthreads();

    // scatter using smem cursors
    const float* xcb = xc + b * NC;
    const float* ycb = yc + b * NC;
    for (int i = tid; i < NC; i += 256) {
        float x = __ldg(&xcb[i]);
        int pos = atomicAdd(&scur[bin_fix(x)], 1);
        g_sx[b * NC + pos] = x;
        g_sy[b * NC + pos] = __ldg(&ycb[i]);
    }
    (void)sstart;
}

// ---------------- K3: psi stage — h0, h1 over truncated window ----------------
__global__ void psi_kernel(const float* __restrict__ pls,
                           const float* __restrict__ pos_) {
    int gw = (blockIdx.x * blockDim.x + threadIdx.x) >> 5;  // one warp per t-point
    int lane = threadIdx.x & 31;
    if (gw >= BATCH * TG) return;
    int b = gw >> 11, i = gw & (TG - 1);

    float lower = g_minmax[0], upper = g_minmax[1];
    float dt = (upper - lower) / (float)(TG - 1);
    float t = lower + i * dt;
    float ls = __ldg(pls), osv = __ldg(pos_);
    float inv2 = 0.5f / (ls * ls);
    float R = fabsf(ls) * RFAC;

    // fixed-bin window (bin width 1.0 over [0,128))
    int blo = min(NBINS - 1, max(0, (int)floorf(t - R)));
    int bhi = min(NBINS - 1, max(0, (int)floorf(t + R)));
    int s = g_starts[b * (NBINS + 1) + blo];
    int e = g_starts[b * (NBINS + 1) + bhi + 1];

    const float* sx = g_sx + b * NC;
    const float* sy = g_sy + b * NC;
    float a0 = 0.f, a1 = 0.f;
    for (int k = s + lane; k < e; k += 32) {
        float xk = __ldg(&sx[k]);
        float yk = __ldg(&sy[k]);
        float d = t - xk;
        float ev = osv * __expf(-d * d * inv2);
        a0 += ev;
        a1 += ev * yk;
    }
    #pragma unroll
    for (int off = 16; off; off >>= 1) {
        a0 += __shfl_xor_sync(0xffffffffu, a0, off);
        a1 += __shfl_xor_sync(0xffffffffu, a1, off);
    }
    if (lane == 0) {
        g_h0[gw] = a0;
        g_h1[gw] = a1 / (a0 + EPS);
    }
}

// ---------------- K4: fused 4-layer conv chain ----------------
#define T_TILE 128
#define HALO   8
#define CW     (T_TILE + 2 * HALO)  // 144
#define CNTH   256

__global__ __launch_bounds__(CNTH) void conv_kernel(
    const float* __restrict__ w1, const float* __restrict__ b1,
    const float* __restrict__ w2, const float* __restrict__ b2,
    const float* __restrict__ w3, const float* __restrict__ b3,
    const float* __restrict__ w4, const float* __restrict__ b4) {
    __shared__ float s0[3][CW];
    __shared__ float s1[16][CW];   // layer1 out, later reused for layer3 out
    __shared__ float s2[32][CW];

    const int tiles = TG / T_TILE;  // 16
    int b = blockIdx.x / tiles;
    int tile = blockIdx.x % tiles;
    int p0 = tile * T_TILE - HALO;  // global pos of local u=0
    int tid = threadIdx.x;

    float lower = g_minmax[0];
    float dt = (g_minmax[1] - lower) / (float)(TG - 1);

    // load input channels (t, h0, h1); zero outside [0, TG)
    for (int u = tid; u < CW; u += CNTH) {
        int p = p0 + u;
        bool in = (p >= 0 && p < TG);
        s0[0][u] = in ? (lower + p * dt) : 0.f;
        s0[1][u] = in ? g_h0[b * TG + p] : 0.f;
        s0[2][u] = in ? g_h1[b * TG + p] : 0.f;
    }
    __syncthreads();

    // layer 1: 3 -> 16, valid u in [2, CW-2)
    {
        const int nv = CW - 4;
        for (int idx = tid; idx < 16 * nv; idx += CNTH) {
            int co = idx / nv, u = 2 + idx % nv;
            float acc = __ldg(&b1[co]);
            #pragma unroll
            for (int ci = 0; ci < 3; ci++)
                #pragma unroll
                for (int k = 0; k < 5; k++)
                    acc += __ldg(&w1[(co * 3 + ci) * 5 + k]) * s0[ci][u - 2 + k];
            int p = p0 + u;
            s1[co][u] = (p >= 0 && p < TG) ? fmaxf(acc, 0.f) : 0.f;
        }
    }
    __syncthreads();

    // layer 2: 16 -> 32, valid u in [4, CW-4)
    {
        const int nv = CW - 8;
        for (int idx = tid; idx < 32 * nv; idx += CNTH) {
            int co = idx / nv, u = 4 + idx % nv;
            float acc = __ldg(&b2[co]);
            #pragma unroll
            for (int ci = 0; ci < 16; ci++)
                #pragma unroll
                for (int k = 0; k < 5; k++)
                    acc += __ldg(&w2[(co * 16 + ci) * 5 + k]) * s1[ci][u - 2 + k];
            int p = p0 + u;
            s2[co][u] = (p >= 0 && p < TG) ? fmaxf(acc, 0.f) : 0.f;
        }
    }
    __syncthreads();

    // layer 3: 32 -> 16, valid u in [6, CW-6); writes back into s1
    {
        const int nv = CW - 12;
        for (int idx = tid; idx < 16 * nv; idx += CNTH) {
            int co = idx / nv, u = 6 + idx % nv;
            float acc = __ldg(&b3[co]);
            #pragma unroll
            for (int ci = 0; ci < 32; ci++)
                #pragma unroll
                for (int k = 0; k < 5; k++)
                    acc += __ldg(&w3[(co * 32 + ci) * 5 + k]) * s2[ci][u - 2 + k];
            int p = p0 + u;
            s1[co][u] = (p >= 0 && p < TG) ? fmaxf(acc, 0.f) : 0.f;
        }
    }
    __syncthreads();

    // layer 4: 16 -> 2, valid u in [HALO, HALO+T_TILE)
    for (int idx = tid; idx < 2 * T_TILE; idx += CNTH) {
        int co = idx / T_TILE, u = HALO + idx % T_TILE;
        float acc = __ldg(&b4[co]);
        #pragma unroll
        for (int ci = 0; ci < 16; ci++)
            #pragma unroll
            for (int k = 0; k < 5; k++)
                acc += __ldg(&w4[(co * 16 + ci) * 5 + k]) * s1[ci][u - 2 + k];
        int p = p0 + u;
        if (co == 0) {
            g_fmu[b * TG + p] = acc;
        } else {
            // softplus(x) = max(x,0) + log1p(exp(-|x|))
            g_fsp[b * TG + p] = fmaxf(acc, 0.f) + log1pf(__expf(-fabsf(acc)));
        }
    }
}

// ---------------- K5: rho stage — mu/sigma over truncated t-window ----------------
__global__ void rho_kernel(const float* __restrict__ xt,
                           const float* __restrict__ pls,
                           const float* __restrict__ pos_,
                           float* __restrict__ out) {
    int gw = (blockIdx.x * blockDim.x + threadIdx.x) >> 5;  // one warp per target
    int lane = threadIdx.x & 31;
    if (gw >= BATCH * NT) return;
    int b = gw >> 11;

    float lower = g_minmax[0];
    float dt = (g_minmax[1] - lower) / (float)(TG - 1);
    float x = __ldg(&xt[gw]);
    float ls = __ldg(pls), osv = __ldg(pos_);
    float inv2 = 0.5f / (ls * ls);
    float R = fabsf(ls) * RFAC;

    int ilo = max(0, (int)ceilf((x - R - lower) / dt));
    int ihi = min(TG - 1, (int)floorf((x + R - lower) / dt));

    const float* fm = g_fmu + b * TG;
    const float* fs = g_fsp + b * TG;
    float mu = 0.f, sg = 0.f;
    for (int i = ilo + lane; i <= ihi; i += 32) {
        float vm = __ldg(&fm[i]);
        float vs = __ldg(&fs[i]);
        float d = x - (lower + i * dt);
        float ev = osv * __expf(-d * d * inv2);
        mu += ev * vm;
        sg += ev * vs;
    }
    #pragma unroll
    for (int off = 16; off; off >>= 1) {
        mu += __shfl_xor_sync(0xffffffffu, mu, off);
        sg += __shfl_xor_sync(0xffffffffu, sg, off);
    }
    if (lane == 0) {
        out[gw * 2 + 0] = mu;
        out[gw * 2 + 1] = sg;
    }
}

// ---------------- launch ----------------
extern "C" void kernel_launch(void* const* d_in, const int* in_sizes, int n_in,
                              void* d_out, int out_size) {
    const float* xc = (const float*)d_in[0];
    const float* yc = (const float*)d_in[1];
    const float* xt = (const float*)d_in[2];
    const float* ls_psi = (const float*)d_in[3];
    const float* os_psi = (const float*)d_in[4];
    const float* ls_rho = (const float*)d_in[5];
    const float* os_rho = (const float*)d_in[6];
    const float* w1 = (const float*)d_in[7];
    const float* b1 = (const float*)d_in[8];
    const float* w2 = (const float*)d_in[9];
    const float* b2 = (const float*)d_in[10];
    const float* w3 = (const float*)d_in[11];
    const float* b3 = (const float*)d_in[12];
    const float* w4 = (const float*)d_in[13];
    const float* b4 = (const float*)d_in[14];
    float* out = (float*)d_out;

    hist_minmax_kernel<<<BATCH, 256>>>(xc, xt);
    prefix_scatter_kernel<<<BATCH, 256>>>(xc, yc);
    psi_kernel<<<(BATCH * TG) / 8, 256>>>(ls_psi, os_psi);
    conv_kernel<<<BATCH * (TG / T_TILE), CNTH>>>(w1, b1, w2, b2, w3, b3, w4, b4);
    rho_kernel<<<(BATCH * NT) / 8, 256>>>(xt, ls_rho, os_rho, out);
}